// round 13
// baseline (speedup 1.0000x reference)
#include <cuda_runtime.h>

// FINAL (locked, 2x reproduced at ~4.6 us): out[i] = 2 * in[i],
// N = 100 floats (25 float4). Launch-latency-bound: ~3.6 us stable
// in-kernel fixed overhead + ~1.0 us harness graph-dispatch gap; the
// 800 B of traffic is <0.2% of wall time (DRAM 0.0%, all pipes 0.0%).
// Twelve profiled rounds exhausted every in-body axis (warp count,
// vector width, thread count, predication, math pipe, load path, store
// policy); all deltas were inside the +-0.5 us jitter band, and the
// plain C++ body beat the inline-asm streaming-store variant in a
// repeated A/B (4.61/4.64 vs 5.12/5.34/5.57 us). Minimal SASS:
// LDG.E.128.CONSTANT -> 4x FMUL -> STG.E.128 -> EXIT.
// 25 threads: HW lane-masks the partial warp, zero predication.
__global__ void __launch_bounds__(32, 1) mul2_kernel(const float4* __restrict__ in,
                                                     float4* __restrict__ out) {
    int i = threadIdx.x;           // 0..24
    float4 v = in[i];
    v.x *= 2.0f; v.y *= 2.0f; v.z *= 2.0f; v.w *= 2.0f;
    out[i] = v;
}

extern "C" void kernel_launch(void* const* d_in, const int* in_sizes, int n_in,
                              void* d_out, int out_size) {
    const float4* in = (const float4*)d_in[0];
    float4* out = (float4*)d_out;
    mul2_kernel<<<1, 25>>>(in, out);
}

// round 14
// speedup vs baseline: 1.1411x; 1.1411x over previous
#include <cuda_runtime.h>

// FINAL (locked): out[i] = 2 * in[i], N = 100 floats (25 float4).
// Launch-latency-bound: in-kernel time is pinned at 3.58-3.68 us (the
// most stable of any variant tested) while wall time draws from a
// +-0.7 us harness graph-dispatch jitter band the .cu cannot reach.
// The 800 B of traffic is <0.2% of wall time (DRAM 0.0%, all pipes
// 0.0%, occ ~1.6% across 13 profiles). Thirteen rounds swept every
// in-body axis (warp count, vector width, thread count, predication,
// math pipe, load path, store policy); all deltas in-band. Minimal
// SASS: LDG.E.128.CONSTANT -> 4x FMUL -> STG.E.128 -> EXIT.
// 25 threads: HW lane-masks the partial warp, zero predication.
__global__ void __launch_bounds__(32, 1) mul2_kernel(const float4* __restrict__ in,
                                                     float4* __restrict__ out) {
    int i = threadIdx.x;           // 0..24
    float4 v = in[i];
    v.x *= 2.0f; v.y *= 2.0f; v.z *= 2.0f; v.w *= 2.0f;
    out[i] = v;
}

extern "C" void kernel_launch(void* const* d_in, const int* in_sizes, int n_in,
                              void* d_out, int out_size) {
    const float4* in = (const float4*)d_in[0];
    float4* out = (float4*)d_out;
    mul2_kernel<<<1, 25>>>(in, out);
}

// round 17
// speedup vs baseline: 1.2917x; 1.1319x over previous
#include <cuda_runtime.h>

// FINAL (locked, 4x reproduced): out[i] = 2 * in[i], N = 100 floats
// (25 float4). Launch-latency-bound: in-kernel time stable at
// 3.58-3.90 us; wall time draws from a +-0.7 us harness graph-dispatch
// jitter band unreachable from the .cu. The 800 B of traffic is <0.2%
// of wall time (DRAM 0.0%, all pipes 0.0%, occ ~1.7% across 14
// profiles). Fourteen rounds swept every in-body axis (warp count,
// vector width, thread count, predication, math pipe, load path, store
// policy); all deltas were inside the jitter band. Minimal SASS:
// LDG.E.128.CONSTANT -> 4x FMUL -> STG.E.128 -> EXIT.
// 25 threads: HW lane-masks the partial warp, zero predication.
__global__ void __launch_bounds__(32, 1) mul2_kernel(const float4* __restrict__ in,
                                                     float4* __restrict__ out) {
    int i = threadIdx.x;           // 0..24
    float4 v = in[i];
    v.x *= 2.0f; v.y *= 2.0f; v.z *= 2.0f; v.w *= 2.0f;
    out[i] = v;
}

extern "C" void kernel_launch(void* const* d_in, const int* in_sizes, int n_in,
                              void* d_out, int out_size) {
    const float4* in = (const float4*)d_in[0];
    float4* out = (float4*)d_out;
    mul2_kernel<<<1, 25>>>(in, out);
}